// round 1
// baseline (speedup 1.0000x reference)
#include <cuda_runtime.h>
#include <cstdint>

#define NU 100000
#define NI 50000
#define NT 150000
#define DD 64
#define EMAX 2000000
#define BB 4096

// ---- static scratch (no allocations allowed) ----
__device__ float d_bufA[(size_t)NT * DD];
__device__ float d_bufB[(size_t)NT * DD];
__device__ float d_acc [(size_t)NT * DD];
__device__ int   d_user_ptr[NU + 1];
__device__ int   d_item_deg[NI];
__device__ int   d_item_ptr[NI + 1];
__device__ int   d_item_cursor[NI];
__device__ int   d_item_cols[EMAX];
__device__ float d_item_vals[EMAX];

// ---------------- CSR build ----------------

__global__ void zero_deg_kernel() {
    int i = blockIdx.x * blockDim.x + threadIdx.x;
    if (i < NI) d_item_deg[i] = 0;
}

// histogram item degrees from first half of edges (cols[e] = item + NU)
__global__ void hist_kernel(const int* __restrict__ cols, int Eu) {
    int e = blockIdx.x * blockDim.x + threadIdx.x;
    if (e < Eu) atomicAdd(&d_item_deg[cols[e] - NU], 1);
}

// one-block exclusive scan over 50000 degrees -> item_ptr, item_cursor
__global__ void scan_kernel(int Eu) {
    const int T = 1024;
    const int CH = (NI + T - 1) / T;  // 49
    __shared__ int ssum[T];
    int t = threadIdx.x;
    int base = t * CH;
    int local = 0;
    for (int j = 0; j < CH; j++) {
        int idx = base + j;
        if (idx < NI) local += d_item_deg[idx];
    }
    ssum[t] = local;
    __syncthreads();
    // Kogge-Stone inclusive scan
    for (int off = 1; off < T; off <<= 1) {
        int v = (t >= off) ? ssum[t - off] : 0;
        __syncthreads();
        ssum[t] += v;
        __syncthreads();
    }
    int run = (t == 0) ? 0 : ssum[t - 1];
    for (int j = 0; j < CH; j++) {
        int idx = base + j;
        if (idx < NI) {
            int dg = d_item_deg[idx];
            d_item_ptr[idx] = run;
            d_item_cursor[idx] = run;
            run += dg;
        }
    }
    if (t == T - 1) d_item_ptr[NI] = run;  // == Eu
}

// scatter first-half edges into item CSR: neighbor = user node id, val
__global__ void scatter_kernel(const int* __restrict__ rows,
                               const int* __restrict__ cols,
                               const float* __restrict__ vals, int Eu) {
    int e = blockIdx.x * blockDim.x + threadIdx.x;
    if (e < Eu) {
        int item = cols[e] - NU;
        int pos = atomicAdd(&d_item_cursor[item], 1);
        d_item_cols[pos] = rows[e];   // user node id (valid index into cur)
        d_item_vals[pos] = vals[e];
    }
}

// user row_ptr via binary search (first half of rows is sorted by user)
__global__ void user_ptr_kernel(const int* __restrict__ rows, int Eu) {
    int r = blockIdx.x * blockDim.x + threadIdx.x;
    if (r > NU) return;
    if (r == NU) { d_user_ptr[NU] = Eu; return; }
    int lo = 0, hi = Eu;
    while (lo < hi) {
        int mid = (lo + hi) >> 1;
        if (rows[mid] < r) lo = mid + 1; else hi = mid;
    }
    d_user_ptr[r] = lo;
}

// ---------------- init: cur = acc = embeds ----------------
__global__ void init_kernel(const float* __restrict__ embeds, float* __restrict__ cur) {
    size_t i = (size_t)blockIdx.x * blockDim.x + threadIdx.x;
    size_t n = (size_t)NT * DD;
    if (i < n) {
        float v = embeds[i];
        cur[i] = v;
        d_acc[i] = v;
    }
}

// ---------------- SpMM: next = A*cur ; acc += next ----------------
__global__ void __launch_bounds__(256) spmm_kernel(const float* __restrict__ cur,
                                                   float* __restrict__ next,
                                                   const int* __restrict__ g_cols,
                                                   const float* __restrict__ g_vals) {
    int warp = (blockIdx.x * blockDim.x + threadIdx.x) >> 5;
    int lane = threadIdx.x & 31;
    if (warp >= NT) return;

    const int* __restrict__ cols;
    const float* __restrict__ vals;
    int s, e;
    if (warp < NU) {
        s = d_user_ptr[warp];
        e = d_user_ptr[warp + 1];
        cols = g_cols;   // item node ids (already + NU)
        vals = g_vals;
    } else {
        int it = warp - NU;
        s = d_item_ptr[it];
        e = d_item_ptr[it + 1];
        cols = d_item_cols;  // user node ids
        vals = d_item_vals;
    }

    float sx = 0.f, sy = 0.f;
    int off = lane * 2;
    int k = s;
    for (; k + 4 <= e; k += 4) {
        int c0 = __ldg(cols + k),     c1 = __ldg(cols + k + 1);
        int c2 = __ldg(cols + k + 2), c3 = __ldg(cols + k + 3);
        float v0 = __ldg(vals + k),     v1 = __ldg(vals + k + 1);
        float v2 = __ldg(vals + k + 2), v3 = __ldg(vals + k + 3);
        float2 x0 = *(const float2*)(cur + (size_t)c0 * DD + off);
        float2 x1 = *(const float2*)(cur + (size_t)c1 * DD + off);
        float2 x2 = *(const float2*)(cur + (size_t)c2 * DD + off);
        float2 x3 = *(const float2*)(cur + (size_t)c3 * DD + off);
        sx = fmaf(v0, x0.x, sx); sy = fmaf(v0, x0.y, sy);
        sx = fmaf(v1, x1.x, sx); sy = fmaf(v1, x1.y, sy);
        sx = fmaf(v2, x2.x, sx); sy = fmaf(v2, x2.y, sy);
        sx = fmaf(v3, x3.x, sx); sy = fmaf(v3, x3.y, sy);
    }
    for (; k < e; k++) {
        int c = __ldg(cols + k);
        float v = __ldg(vals + k);
        float2 x = *(const float2*)(cur + (size_t)c * DD + off);
        sx = fmaf(v, x.x, sx); sy = fmaf(v, x.y, sy);
    }

    size_t o = (size_t)warp * DD + off;
    float2 outv; outv.x = sx; outv.y = sy;
    *(float2*)(next + o) = outv;
    float2 a = *(float2*)(d_acc + o);
    a.x += sx; a.y += sy;
    *(float2*)(d_acc + o) = a;
}

// ---------------- final gather ----------------
__global__ void gather_kernel(const int* __restrict__ users,
                              const int* __restrict__ pos,
                              const int* __restrict__ neg,
                              float* __restrict__ out) {
    int warp = (blockIdx.x * blockDim.x + threadIdx.x) >> 5;
    int lane = threadIdx.x & 31;
    if (warp >= 3 * BB) return;
    int b = warp & (BB - 1);
    int which = warp >> 12;
    int node;
    if (which == 0)      node = users[b];
    else if (which == 1) node = NU + pos[b];
    else                 node = NU + neg[b];
    int off = lane * 2;
    float2 v = *(const float2*)(d_acc + (size_t)node * DD + off);
    float2 o; o.x = v.x * 0.25f; o.y = v.y * 0.25f;
    *(float2*)(out + (size_t)warp * DD + off) = o;
}

// ---------------- launch ----------------
extern "C" void kernel_launch(void* const* d_in, const int* in_sizes, int n_in,
                              void* d_out, int out_size) {
    const float* embeds = (const float*)d_in[0];
    const float* vals   = (const float*)d_in[1];
    const int*   rows   = (const int*)d_in[2];
    const int*   cols   = (const int*)d_in[3];
    const int*   users  = (const int*)d_in[4];
    const int*   pos    = (const int*)d_in[5];
    const int*   neg    = (const int*)d_in[6];
    float* out = (float*)d_out;

    int Eu = in_sizes[2] / 2;  // unique (u,i) edges; first half is user-sorted

    float *bufA, *bufB;
    cudaGetSymbolAddress((void**)&bufA, d_bufA);
    cudaGetSymbolAddress((void**)&bufB, d_bufB);

    // CSR build (item side) + user row_ptr
    zero_deg_kernel<<<(NI + 255) / 256, 256>>>();
    hist_kernel<<<(Eu + 255) / 256, 256>>>(cols, Eu);
    scan_kernel<<<1, 1024>>>(Eu);
    scatter_kernel<<<(Eu + 255) / 256, 256>>>(rows, cols, vals, Eu);
    user_ptr_kernel<<<(NU + 256) / 256, 256>>>(rows, Eu);

    // init cur = acc = embeds
    {
        size_t n = (size_t)NT * DD;
        init_kernel<<<(int)((n + 255) / 256), 256>>>(embeds, bufA);
    }

    // 3 propagation layers
    float* cur = bufA;
    float* nxt = bufB;
    int spmm_blocks = (NT * 32 + 255) / 256;
    for (int l = 0; l < 3; l++) {
        spmm_kernel<<<spmm_blocks, 256>>>(cur, nxt, cols, vals);
        float* t = cur; cur = nxt; nxt = t;
    }

    // gather outputs (mean = acc / 4)
    gather_kernel<<<(3 * BB * 32 + 255) / 256, 256>>>(users, pos, neg, out);
}

// round 4
// speedup vs baseline: 1.1525x; 1.1525x over previous
#include <cuda_runtime.h>
#include <cuda_fp16.h>
#include <cstdint>

#define NU 100000
#define NI 50000
#define NT 150000
#define DD 64
#define DH 32          // half2 per row
#define EMAX 2000000
#define BB 4096

// ---- static scratch (no allocations allowed) ----
__device__ __half d_emb_h[(size_t)NT * DD];
__device__ __half d_c1[(size_t)NT * DD];
__device__ __half d_c2[(size_t)NT * DD];
__device__ __half d_c3[(size_t)NT * DD];
__device__ int    d_user_ptr[NU + 1];
__device__ int    d_item_deg[NI];
__device__ int    d_item_ptr[NI + 1];
__device__ int    d_item_cursor[NI];
__device__ int2   d_item_edge[EMAX];   // {user_node, float_bits(val)}

// ---------------- CSR build ----------------

__global__ void zero_deg_kernel() {
    int i = blockIdx.x * blockDim.x + threadIdx.x;
    if (i < NI) d_item_deg[i] = 0;
}

__global__ void hist_kernel(const int* __restrict__ cols, int Eu) {
    int e = blockIdx.x * blockDim.x + threadIdx.x;
    if (e < Eu) atomicAdd(&d_item_deg[cols[e] - NU], 1);
}

// one-block exclusive scan over NI degrees -> item_ptr, item_cursor
__global__ void scan_kernel(int Eu) {
    const int T = 1024;
    const int CH = (NI + T - 1) / T;
    __shared__ int ssum[T];
    int t = threadIdx.x;
    int base = t * CH;
    int local = 0;
    for (int j = 0; j < CH; j++) {
        int idx = base + j;
        if (idx < NI) local += d_item_deg[idx];
    }
    ssum[t] = local;
    __syncthreads();
    for (int off = 1; off < T; off <<= 1) {
        int v = (t >= off) ? ssum[t - off] : 0;
        __syncthreads();
        ssum[t] += v;
        __syncthreads();
    }
    int run = (t == 0) ? 0 : ssum[t - 1];
    for (int j = 0; j < CH; j++) {
        int idx = base + j;
        if (idx < NI) {
            int dg = d_item_deg[idx];
            d_item_ptr[idx] = run;
            d_item_cursor[idx] = run;
            run += dg;
        }
    }
    if (t == T - 1) d_item_ptr[NI] = run;
}

// scatter first-half edges into packed item CSR (one 8B write per edge)
__global__ void scatter_kernel(const int* __restrict__ rows,
                               const int* __restrict__ cols,
                               const float* __restrict__ vals, int Eu) {
    int e = blockIdx.x * blockDim.x + threadIdx.x;
    if (e < Eu) {
        int item = cols[e] - NU;
        int pos = atomicAdd(&d_item_cursor[item], 1);
        d_item_edge[pos] = make_int2(rows[e], __float_as_int(vals[e]));
    }
}

// user row_ptr via binary search (first half of rows is sorted by user)
__global__ void user_ptr_kernel(const int* __restrict__ rows, int Eu) {
    int r = blockIdx.x * blockDim.x + threadIdx.x;
    if (r > NU) return;
    if (r == NU) { d_user_ptr[NU] = Eu; return; }
    int lo = 0, hi = Eu;
    while (lo < hi) {
        int mid = (lo + hi) >> 1;
        if (rows[mid] < r) lo = mid + 1; else hi = mid;
    }
    d_user_ptr[r] = lo;
}

// ---------------- convert embeds (fp32) -> half ----------------
__global__ void convert_kernel(const float* __restrict__ embeds) {
    size_t i = (size_t)blockIdx.x * blockDim.x + threadIdx.x;
    size_t n = (size_t)NT * DH;
    if (i < n) {
        float2 v = ((const float2*)embeds)[i];
        ((__half2*)d_emb_h)[i] = __float22half2_rn(v);
    }
}

// ---------------- SpMM user rows: next[u] = sum val * cur[item] ----------------
__global__ void __launch_bounds__(256) spmm_user_kernel(const __half* __restrict__ cur,
                                                        __half* __restrict__ next,
                                                        const int* __restrict__ g_cols,
                                                        const float* __restrict__ g_vals) {
    int warp = (blockIdx.x * blockDim.x + threadIdx.x) >> 5;
    int lane = threadIdx.x & 31;
    if (warp >= NU) return;
    int s = d_user_ptr[warp];
    int e = d_user_ptr[warp + 1];

    const __half2* __restrict__ cur2 = (const __half2*)cur;
    float sx = 0.f, sy = 0.f;
    int k = s;
    for (; k + 4 <= e; k += 4) {
        int c0 = __ldg(g_cols + k),     c1 = __ldg(g_cols + k + 1);
        int c2 = __ldg(g_cols + k + 2), c3 = __ldg(g_cols + k + 3);
        float v0 = __ldg(g_vals + k),     v1 = __ldg(g_vals + k + 1);
        float v2 = __ldg(g_vals + k + 2), v3 = __ldg(g_vals + k + 3);
        float2 x0 = __half22float2(cur2[(size_t)c0 * DH + lane]);
        float2 x1 = __half22float2(cur2[(size_t)c1 * DH + lane]);
        float2 x2 = __half22float2(cur2[(size_t)c2 * DH + lane]);
        float2 x3 = __half22float2(cur2[(size_t)c3 * DH + lane]);
        sx = fmaf(v0, x0.x, sx); sy = fmaf(v0, x0.y, sy);
        sx = fmaf(v1, x1.x, sx); sy = fmaf(v1, x1.y, sy);
        sx = fmaf(v2, x2.x, sx); sy = fmaf(v2, x2.y, sy);
        sx = fmaf(v3, x3.x, sx); sy = fmaf(v3, x3.y, sy);
    }
    for (; k < e; k++) {
        int c = __ldg(g_cols + k);
        float v = __ldg(g_vals + k);
        float2 x = __half22float2(cur2[(size_t)c * DH + lane]);
        sx = fmaf(v, x.x, sx); sy = fmaf(v, x.y, sy);
    }
    ((__half2*)next)[(size_t)warp * DH + lane] = __float22half2_rn(make_float2(sx, sy));
}

// ---------------- SpMM item rows: next[item+NU] = sum val * cur[user] ----------------
__global__ void __launch_bounds__(256) spmm_item_kernel(const __half* __restrict__ cur,
                                                        __half* __restrict__ next) {
    int warp = (blockIdx.x * blockDim.x + threadIdx.x) >> 5;
    int lane = threadIdx.x & 31;
    if (warp >= NI) return;
    int s = d_item_ptr[warp];
    int e = d_item_ptr[warp + 1];

    const __half2* __restrict__ cur2 = (const __half2*)cur;
    float sx = 0.f, sy = 0.f;
    int k = s;
    for (; k + 4 <= e; k += 4) {
        int2 e0 = d_item_edge[k],     e1 = d_item_edge[k + 1];
        int2 e2 = d_item_edge[k + 2], e3 = d_item_edge[k + 3];
        float2 x0 = __half22float2(cur2[(size_t)e0.x * DH + lane]);
        float2 x1 = __half22float2(cur2[(size_t)e1.x * DH + lane]);
        float2 x2 = __half22float2(cur2[(size_t)e2.x * DH + lane]);
        float2 x3 = __half22float2(cur2[(size_t)e3.x * DH + lane]);
        float v0 = __int_as_float(e0.y), v1 = __int_as_float(e1.y);
        float v2 = __int_as_float(e2.y), v3 = __int_as_float(e3.y);
        sx = fmaf(v0, x0.x, sx); sy = fmaf(v0, x0.y, sy);
        sx = fmaf(v1, x1.x, sx); sy = fmaf(v1, x1.y, sy);
        sx = fmaf(v2, x2.x, sx); sy = fmaf(v2, x2.y, sy);
        sx = fmaf(v3, x3.x, sx); sy = fmaf(v3, x3.y, sy);
    }
    for (; k < e; k++) {
        int2 ed = d_item_edge[k];
        float2 x = __half22float2(cur2[(size_t)ed.x * DH + lane]);
        float v = __int_as_float(ed.y);
        sx = fmaf(v, x.x, sx); sy = fmaf(v, x.y, sy);
    }
    ((__half2*)next)[((size_t)warp + NU) * DH + lane] = __float22half2_rn(make_float2(sx, sy));
}

// ---------------- final gather: out = (embeds + c1 + c2 + c3)/4 ----------------
__global__ void gather_kernel(const float* __restrict__ embeds,
                              const int* __restrict__ users,
                              const int* __restrict__ pos,
                              const int* __restrict__ neg,
                              float* __restrict__ out) {
    int warp = (blockIdx.x * blockDim.x + threadIdx.x) >> 5;
    int lane = threadIdx.x & 31;
    if (warp >= 3 * BB) return;
    int b = warp & (BB - 1);
    int which = warp >> 12;
    int node;
    if (which == 0)      node = users[b];
    else if (which == 1) node = NU + pos[b];
    else                 node = NU + neg[b];
    size_t ro = (size_t)node * DH + lane;
    float2 ev = ((const float2*)embeds)[ro];
    float2 a1 = __half22float2(((const __half2*)d_c1)[ro]);
    float2 a2 = __half22float2(((const __half2*)d_c2)[ro]);
    float2 a3 = __half22float2(((const __half2*)d_c3)[ro]);
    float2 o;
    o.x = (ev.x + a1.x + a2.x + a3.x) * 0.25f;
    o.y = (ev.y + a1.y + a2.y + a3.y) * 0.25f;
    ((float2*)out)[(size_t)warp * DH + lane] = o;
}

// ---------------- launch ----------------
extern "C" void kernel_launch(void* const* d_in, const int* in_sizes, int n_in,
                              void* d_out, int out_size) {
    const float* embeds = (const float*)d_in[0];
    const float* vals   = (const float*)d_in[1];
    const int*   rows   = (const int*)d_in[2];
    const int*   cols   = (const int*)d_in[3];
    const int*   users  = (const int*)d_in[4];
    const int*   pos    = (const int*)d_in[5];
    const int*   neg    = (const int*)d_in[6];
    float* out = (float*)d_out;

    int Eu = in_sizes[2] / 2;

    __half *emb_h, *c1, *c2, *c3;
    cudaGetSymbolAddress((void**)&emb_h, d_emb_h);
    cudaGetSymbolAddress((void**)&c1, d_c1);
    cudaGetSymbolAddress((void**)&c2, d_c2);
    cudaGetSymbolAddress((void**)&c3, d_c3);

    // CSR build (item side) + user row_ptr + fp16 conversion
    zero_deg_kernel<<<(NI + 255) / 256, 256>>>();
    hist_kernel<<<(Eu + 255) / 256, 256>>>(cols, Eu);
    scan_kernel<<<1, 1024>>>(Eu);
    scatter_kernel<<<(Eu + 255) / 256, 256>>>(rows, cols, vals, Eu);
    user_ptr_kernel<<<(NU + 256) / 256, 256>>>(rows, Eu);
    {
        size_t n = (size_t)NT * DH;
        convert_kernel<<<(int)((n + 255) / 256), 256>>>(embeds);
    }

    // 3 propagation layers (cur0 = emb_h)
    const __half* curp = emb_h;
    __half* bufs[3] = {c1, c2, c3};
    int ublocks = (NU * 32 + 255) / 256;
    int iblocks = (NI * 32 + 255) / 256;
    for (int l = 0; l < 3; l++) {
        __half* nxt = bufs[l];
        spmm_user_kernel<<<ublocks, 256>>>(curp, nxt, cols, vals);
        spmm_item_kernel<<<iblocks, 256>>>(curp, nxt);
        curp = nxt;
    }

    // gather outputs
    gather_kernel<<<(3 * BB * 32 + 255) / 256, 256>>>(embeds, users, pos, neg, out);
}